// round 12
// baseline (speedup 1.0000x reference)
#include <cuda_runtime.h>
#include <cuda_fp16.h>
#include <math.h>
#include <stdint.h>

#define B_ 2
#define T_ 2048
#define DIM_ 2048
#define H_ 16
#define HD_ 128
#define BT_ (B_ * T_)

// ---------------------------------------------------------------------------
// Scratch (alloc-free rules: __device__ globals)
// ---------------------------------------------------------------------------
static __device__ float g_q[(size_t)BT_ * DIM_];     // Q after GEMM (pre-RoPE)
static __device__ __half g_qh[(size_t)BT_ * DIM_];   // roped+scaled Q (fp16)
static __device__ __half g_kh[(size_t)BT_ * HD_];    // roped K (fp16) [B,T,HD]
static __device__ __half g_vth[(size_t)BT_ * HD_];   // V^T hi/lo fp16 [B,HD,T]
static __device__ __half g_vtl[(size_t)BT_ * HD_];
// fp16 natural-order operands for projection GEMMs
static __device__ __half g_xt[(size_t)BT_ * DIM_];
static __device__ __half g_at[(size_t)BT_ * DIM_];   // attn out (written by flash)
static __device__ __half g_wqt[(size_t)DIM_ * DIM_]; // W^T [N][K]
static __device__ __half g_wot[(size_t)DIM_ * DIM_];
static __device__ __half g_wkt[(size_t)HD_ * DIM_];
static __device__ __half g_wvt[(size_t)HD_ * DIM_];

// ---------------------------------------------------------------------------
// helpers
// ---------------------------------------------------------------------------
__device__ __forceinline__ uint32_t smem_u32(const void* p) {
    uint32_t a;
    asm("{ .reg .u64 t; cvta.to.shared.u64 t, %1; cvt.u32.u64 %0, t; }" : "=r"(a) : "l"(p));
    return a;
}
__device__ __forceinline__ void mmafp(float* c, uint32_t a0, uint32_t a1, uint32_t a2,
                                      uint32_t a3, uint32_t b0, uint32_t b1) {
    asm volatile(
        "mma.sync.aligned.m16n8k16.row.col.f32.f16.f16.f32 "
        "{%0,%1,%2,%3},{%4,%5,%6,%7},{%8,%9},{%0,%1,%2,%3};"
        : "+f"(c[0]), "+f"(c[1]), "+f"(c[2]), "+f"(c[3])
        : "r"(a0), "r"(a1), "r"(a2), "r"(a3), "r"(b0), "r"(b1));
}
__device__ __forceinline__ uint32_t pack2h(float a, float b) {
    __half2 p = __floats2half2_rn(a, b);
    return *(uint32_t*)&p;
}
#define LDSM4(r0, r1, r2, r3, a) \
    asm volatile("ldmatrix.sync.aligned.m8n8.x4.shared.b16 {%0,%1,%2,%3}, [%4];" \
                 : "=r"(r0), "=r"(r1), "=r"(r2), "=r"(r3) : "r"(a))
#define CPA16(d, s) asm volatile("cp.async.cg.shared.global [%0], [%1], 16;" :: "r"(d), "l"(s))
#define CPCOMMIT()  asm volatile("cp.async.commit_group;" ::: "memory")
#define CPWAIT1()   asm volatile("cp.async.wait_group 1;" ::: "memory")
#define CPWAIT0()   asm volatile("cp.async.wait_group 0;" ::: "memory")

// ---------------------------------------------------------------------------
// Prep: plain fp32 -> fp16
// ---------------------------------------------------------------------------
__global__ __launch_bounds__(256) void conv_act(const float* __restrict__ src)
{
    size_t i = (size_t)blockIdx.x * 256 + threadIdx.x;   // 8 floats per thread
    size_t base = i * 8;
    float4 v0 = *(const float4*)(src + base);
    float4 v1 = *(const float4*)(src + base + 4);
    uint4 o = make_uint4(pack2h(v0.x, v0.y), pack2h(v0.z, v0.w),
                         pack2h(v1.x, v1.y), pack2h(v1.z, v1.w));
    *(uint4*)(g_xt + base) = o;
}

// W [K=2048][N] -> Wt [N][K] fp16 (transpose); blockIdx.z picks (W0,W1)
__global__ void conv_w2(const float* __restrict__ W0, const float* __restrict__ W1,
                        int N, int wsel0, int wsel1)
{
    __shared__ float t[32][33];
    const float* W = blockIdx.z ? W1 : W0;
    int wsel = blockIdx.z ? wsel1 : wsel0;
    __half* dst = (wsel == 0) ? g_wqt : (wsel == 1) ? g_wkt : (wsel == 2) ? g_wvt : g_wot;
    int n0 = blockIdx.x * 32, k0 = blockIdx.y * 32;
    int tx = threadIdx.x, ty = threadIdx.y;          // (32, 2)
#pragma unroll
    for (int r = ty; r < 32; r += 2)
        t[r][tx] = W[(size_t)(k0 + r) * N + n0 + tx];
    __syncthreads();
    float f[16];
#pragma unroll
    for (int j = 0; j < 16; j++) f[j] = t[ty * 16 + j][tx];
    uint4 o0 = make_uint4(pack2h(f[0], f[1]), pack2h(f[2], f[3]),
                          pack2h(f[4], f[5]), pack2h(f[6], f[7]));
    uint4 o1 = make_uint4(pack2h(f[8], f[9]), pack2h(f[10], f[11]),
                          pack2h(f[12], f[13]), pack2h(f[14], f[15]));
    size_t o = (size_t)(n0 + tx) * DIM_ + k0 + ty * 16;
    *(uint4*)(dst + o)     = o0;
    *(uint4*)(dst + o + 8) = o1;
}

// ---------------------------------------------------------------------------
// FP16 GEMM: ldmatrix + XOR-swizzled smem + 3-stage k64 cp.async pipeline.
// mode 0: fused QKV — grid.x 0..15 -> Q tile; 16 -> K; 17 -> V.  A = g_xt.
// mode 1: Wo — A = g_at, C = out.
// 128x128 tile, 256 thr (8 warps 2x4, warp 64x32).
// smem per stage: A 128x64 halfs (16KB) + B same; 3 stages = 96KB.
// ---------------------------------------------------------------------------
#define NSTG 3
#define STGB 16384           // bytes per matrix per stage
#define BOFF (NSTG * STGB)   // B region offset
static const int GEMM_SMEM = 2 * NSTG * STGB;   // 98304

__global__ __launch_bounds__(256, 2) void hgemm(
    int mode, float* __restrict__ pk, float* __restrict__ pv, float* __restrict__ outp)
{
    extern __shared__ __half smh[];
    const __half* Ag;
    const __half* Bg;
    float* C;
    int N, bn0;
    if (mode == 0) {
        Ag = g_xt;
        if (blockIdx.x < 16)      { Bg = g_wqt; C = g_q; N = DIM_; bn0 = blockIdx.x * 128; }
        else if (blockIdx.x == 16){ Bg = g_wkt; C = pk;  N = HD_;  bn0 = 0; }
        else                      { Bg = g_wvt; C = pv;  N = HD_;  bn0 = 0; }
    } else {
        Ag = g_at; Bg = g_wot; C = outp; N = DIM_; bn0 = blockIdx.x * 128;
    }

    const int K = DIM_;
    int tid = threadIdx.x;
    int bm0 = blockIdx.y * 128;
    int warp = tid >> 5, lane = tid & 31;
    int wm = (warp & 1) * 64, wn = (warp >> 1) * 32;
    int lr = lane >> 2, lc = lane & 3;
    uint32_t sbase = smem_u32(smh);

    float acc[4][4][4];
#pragma unroll
    for (int mt = 0; mt < 4; mt++)
#pragma unroll
        for (int nt = 0; nt < 4; nt++)
#pragma unroll
            for (int i = 0; i < 4; i++) acc[mt][nt][i] = 0.f;

    // ---- cp.async geometry: thread t -> row t>>1, 4 chunks of 16B ----
    int crow = tid >> 1;
    int cuh = (tid & 1) * 4;                     // first unit (of 8 per row)
    uint32_t cdst[4];
#pragma unroll
    for (int i = 0; i < 4; i++)
        cdst[i] = (uint32_t)(crow * 128 + (((cuh + i) ^ (crow & 7)) * 16));
    const __half* aS = Ag + (size_t)(bm0 + crow) * K + cuh * 8;
    const __half* bS = Bg + (size_t)(bn0 + crow) * K + cuh * 8;

#define ISSUE(st, k0) do { \
        uint32_t ab = sbase + (uint32_t)((st) * STGB); \
        uint32_t bb = ab + (uint32_t)BOFF; \
        CPA16(ab + cdst[0], aS + (k0));          CPA16(ab + cdst[1], aS + (k0) + 8); \
        CPA16(ab + cdst[2], aS + (k0) + 16);     CPA16(ab + cdst[3], aS + (k0) + 24); \
        CPA16(bb + cdst[0], bS + (k0));          CPA16(bb + cdst[1], bS + (k0) + 8); \
        CPA16(bb + cdst[2], bS + (k0) + 16);     CPA16(bb + cdst[3], bS + (k0) + 24); \
        CPCOMMIT(); \
    } while (0)

    // ---- ldmatrix per-lane addressing ----
    int swz = lane & 7;
    int mhalf = (lane >> 3) & 1;     // matrix&1 -> +8 rows
    int uhi = lane >> 4;             // matrix>>1 -> +1 k-unit
    uint32_t arowb = (uint32_t)((wm + mhalf * 8 + swz) * 128);
    uint32_t browb = (uint32_t)((wn + mhalf * 8 + swz) * 128);

    ISSUE(0, 0);
    ISSUE(1, 64);

    const int nT = K / 64;   // 32
    for (int t = 0; t < nT; t++) {
        if (t + 1 < nT) CPWAIT1(); else CPWAIT0();
        __syncthreads();
        if (t + 2 < nT) ISSUE((t + 2) % NSTG, (t + 2) * 64);

        int p = t % NSTG;
        uint32_t ab = sbase + (uint32_t)(p * STGB);
        uint32_t bb = ab + (uint32_t)BOFF;
#pragma unroll
        for (int kb = 0; kb < 4; kb++) {
            uint32_t koff = (uint32_t)(((kb * 2 + uhi) ^ swz) * 16);
            uint32_t br0[4], br1[4];
            LDSM4(br0[0], br0[1], br0[2], br0[3], bb + browb + koff);
            LDSM4(br1[0], br1[1], br1[2], br1[3], bb + browb + 2048 + koff);
#pragma unroll
            for (int mt = 0; mt < 4; mt++) {
                uint32_t ar[4];
                LDSM4(ar[0], ar[1], ar[2], ar[3], ab + arowb + mt * 2048 + koff);
                mmafp(acc[mt][0], ar[0], ar[1], ar[2], ar[3], br0[0], br0[2]);
                mmafp(acc[mt][1], ar[0], ar[1], ar[2], ar[3], br0[1], br0[3]);
                mmafp(acc[mt][2], ar[0], ar[1], ar[2], ar[3], br1[0], br1[2]);
                mmafp(acc[mt][3], ar[0], ar[1], ar[2], ar[3], br1[1], br1[3]);
            }
        }
    }

#pragma unroll
    for (int mt = 0; mt < 4; mt++) {
        int row = bm0 + wm + mt * 16 + lr;
#pragma unroll
        for (int nt = 0; nt < 4; nt++) {
            int col = bn0 + wn + nt * 8 + lc * 2;
            *(float2*)&C[(size_t)row * N + col]       = make_float2(acc[mt][nt][0], acc[mt][nt][1]);
            *(float2*)&C[(size_t)(row + 8) * N + col] = make_float2(acc[mt][nt][2], acc[mt][nt][3]);
        }
    }
#undef ISSUE
}

// ---------------------------------------------------------------------------
// RoPE + conversion kernels
// ---------------------------------------------------------------------------
__global__ __launch_bounds__(256) void rope_q_split()
{
    int idx = blockIdx.x * 256 + threadIdx.x;
    int j = idx & 63;
    int h = (idx >> 6) & (H_ - 1);
    int t = (idx >> 10) & (T_ - 1);
    int b = idx >> 21;
    const float scale = 0.08838834764831845f;
    float inv = powf(10000.0f, -(float)j * (1.0f / 64.0f));
    float ang = (float)t * inv;
    float sv, cv;
    sincosf(ang, &sv, &cv);
    size_t base = (((size_t)b * T_ + t) * H_ + h) * (size_t)HD_;
    float x1 = g_q[base + j], x2 = g_q[base + j + 64];
    g_qh[base + j]      = __float2half((x1 * cv - x2 * sv) * scale);
    g_qh[base + j + 64] = __float2half((x2 * cv + x1 * sv) * scale);
}

__global__ __launch_bounds__(256) void rope_k_split(float* __restrict__ kb)
{
    int idx = blockIdx.x * 256 + threadIdx.x;
    int j = idx & 63;
    int t = (idx >> 6) & (T_ - 1);
    int b = idx >> 17;
    float inv = powf(10000.0f, -(float)j * (1.0f / 64.0f));
    float ang = (float)t * inv;
    float sv, cv;
    sincosf(ang, &sv, &cv);
    size_t base = ((size_t)b * T_ + t) * (size_t)HD_;
    float x1 = kb[base + j], x2 = kb[base + j + 64];
    float r1 = x1 * cv - x2 * sv;
    float r2 = x2 * cv + x1 * sv;
    kb[base + j] = r1;              // present_k output (fp32)
    kb[base + j + 64] = r2;
    g_kh[base + j]      = __float2half(r1);
    g_kh[base + j + 64] = __float2half(r2);
}

// V: [B,T,HD] fp32 -> [B,HD,T] fp16 hi/lo (transpose + split)
__global__ void v_split_t(const float* __restrict__ vb)
{
    __shared__ float tile[32][33];
    int t0 = blockIdx.x * 32, d0 = blockIdx.y * 32, b = blockIdx.z;
    int tx = threadIdx.x, ty = threadIdx.y;
#pragma unroll
    for (int r = ty; r < 32; r += 8)
        tile[r][tx] = vb[((size_t)b * T_ + t0 + r) * HD_ + d0 + tx];
    __syncthreads();
#pragma unroll
    for (int r = ty; r < 32; r += 8) {
        float v = tile[tx][r];
        __half hh = __float2half(v);
        size_t o = ((size_t)b * HD_ + d0 + r) * T_ + t0 + tx;
        g_vth[o] = hh;
        g_vtl[o] = __float2half(v - __half2float(hh));
    }
}

// ---------------------------------------------------------------------------
// Flash attention: S = fp16 x1, PV = fp16 x2 (V hi/lo). BQ=BKV=64, 128 thr.
// Output written as natural-order fp16 into g_at (Wo A-operand).
// ---------------------------------------------------------------------------
#define FBQ 64
#define FBKV 64
#define KSTR 136
#define VSTR 72

__global__ __launch_bounds__(128, 2) void flash_mixed()
{
    extern __shared__ __half smh2[];
    __half* Kh  = smh2;                     // [64][KSTR]
    __half* VTh = Kh + 64 * KSTR;           // [128][VSTR]
    __half* VTl = VTh + 128 * VSTR;
    __half* Ph  = VTl + 128 * VSTR;         // [64][VSTR]

    int tid = threadIdx.x;
    int w = tid >> 5, lane = tid & 31;
    int lr = lane >> 2, lc = lane & 3;
    int qb = blockIdx.x;
    int bh = (int)blockIdx.y;
    int b = bh >> 4, h = bh & 15;
    int q0 = qb * FBQ;
    int rb = w * 16;

    // Q fragments (fp16) in registers
    uint32_t qf[8][4];
    {
        const __half* qh = g_qh + (((size_t)b * T_ + q0) * H_ + h) * (size_t)HD_;
#pragma unroll
        for (int kk = 0; kk < 8; kk++) {
            int ke = kk * 16;
            qf[kk][0] = *(const uint32_t*)&qh[(size_t)(rb + lr) * DIM_ + ke + 2 * lc];
            qf[kk][1] = *(const uint32_t*)&qh[(size_t)(rb + lr + 8) * DIM_ + ke + 2 * lc];
            qf[kk][2] = *(const uint32_t*)&qh[(size_t)(rb + lr) * DIM_ + ke + 2 * lc + 8];
            qf[kk][3] = *(const uint32_t*)&qh[(size_t)(rb + lr + 8) * DIM_ + ke + 2 * lc + 8];
        }
    }

    float m0r = -1e30f, m1r = -1e30f, l0r = 0.f, l1r = 0.f;
    float O[16][4];
#pragma unroll
    for (int i = 0; i < 16; i++)
#pragma unroll
        for (int j = 0; j < 4; j++) O[i][j] = 0.f;

    const __half* kbh = g_kh + (size_t)b * T_ * HD_;
    const __half* vbh = g_vth + (size_t)b * HD_ * T_;
    const __half* vbl = g_vtl + (size_t)b * HD_ * T_;

    for (int kt = 0; kt <= qb; kt++) {
        int k0 = kt * FBKV;
        __syncthreads();

#pragma unroll
        for (int it = 0; it < 8; it++) {
            int i = tid + it * 128;
            int r = i >> 4, c = (i & 15) * 8;
            *(uint4*)&Kh[r * KSTR + c] = *(const uint4*)&kbh[(size_t)(k0 + r) * HD_ + c];
        }
#pragma unroll
        for (int it = 0; it < 8; it++) {
            int i = tid + it * 128;
            int r = i >> 3, c = (i & 7) * 8;
            size_t ga = (size_t)r * T_ + k0 + c;
            *(uint4*)&VTh[r * VSTR + c] = *(const uint4*)&vbh[ga];
            *(uint4*)&VTl[r * VSTR + c] = *(const uint4*)&vbl[ga];
        }
        __syncthreads();

        float sacc[8][4];
#pragma unroll
        for (int nt = 0; nt < 8; nt++)
#pragma unroll
            for (int j = 0; j < 4; j++) sacc[nt][j] = 0.f;

#pragma unroll
        for (int kk = 0; kk < 8; kk++) {
            int ke = kk * 16;
#pragma unroll
            for (int nt = 0; nt < 8; nt++) {
                int n = nt * 8 + lr;
                uint32_t b0 = *(uint32_t*)&Kh[n * KSTR + ke + 2 * lc];
                uint32_t b1 = *(uint32_t*)&Kh[n * KSTR + ke + 2 * lc + 8];
                mmafp(sacc[nt], qf[kk][0], qf[kk][1], qf[kk][2], qf[kk][3], b0, b1);
            }
        }

        if (kt == qb) {
            int r0g = rb + lr, r1g = r0g + 8;
#pragma unroll
            for (int nt = 0; nt < 8; nt++) {
                int cg = nt * 8 + 2 * lc;
                if (cg > r0g)     sacc[nt][0] = -1e30f;
                if (cg + 1 > r0g) sacc[nt][1] = -1e30f;
                if (cg > r1g)     sacc[nt][2] = -1e30f;
                if (cg + 1 > r1g) sacc[nt][3] = -1e30f;
            }
        }

        float mt0 = -1e30f, mt1 = -1e30f;
#pragma unroll
        for (int nt = 0; nt < 8; nt++) {
            mt0 = fmaxf(mt0, fmaxf(sacc[nt][0], sacc[nt][1]));
            mt1 = fmaxf(mt1, fmaxf(sacc[nt][2], sacc[nt][3]));
        }
        mt0 = fmaxf(mt0, __shfl_xor_sync(0xffffffff, mt0, 1));
        mt0 = fmaxf(mt0, __shfl_xor_sync(0xffffffff, mt0, 2));
        mt1 = fmaxf(mt1, __shfl_xor_sync(0xffffffff, mt1, 1));
        mt1 = fmaxf(mt1, __shfl_xor_sync(0xffffffff, mt1, 2));

        float mn0 = fmaxf(m0r, mt0), mn1 = fmaxf(m1r, mt1);
        float al0f = __expf(m0r - mn0), al1f = __expf(m1r - mn1);
        m0r = mn0; m1r = mn1;

        float rs0 = 0.f, rs1 = 0.f;
#pragma unroll
        for (int nt = 0; nt < 8; nt++) {
            float p0 = __expf(sacc[nt][0] - mn0);
            float p1 = __expf(sacc[nt][1] - mn0);
            float p2 = __expf(sacc[nt][2] - mn1);
            float p3 = __expf(sacc[nt][3] - mn1);
            rs0 += p0 + p1; rs1 += p2 + p3;
            *(uint32_t*)&Ph[(rb + lr) * VSTR + nt * 8 + 2 * lc]     = pack2h(p0, p1);
            *(uint32_t*)&Ph[(rb + lr + 8) * VSTR + nt * 8 + 2 * lc] = pack2h(p2, p3);
        }
        rs0 += __shfl_xor_sync(0xffffffff, rs0, 1);
        rs0 += __shfl_xor_sync(0xffffffff, rs0, 2);
        rs1 += __shfl_xor_sync(0xffffffff, rs1, 1);
        rs1 += __shfl_xor_sync(0xffffffff, rs1, 2);
        l0r = l0r * al0f + rs0;
        l1r = l1r * al1f + rs1;

#pragma unroll
        for (int nt = 0; nt < 16; nt++) {
            O[nt][0] *= al0f; O[nt][1] *= al0f;
            O[nt][2] *= al1f; O[nt][3] *= al1f;
        }
        __syncwarp();

        // O += P @ V (fp16 x2: V hi + V lo)
#pragma unroll
        for (int kk = 0; kk < 4; kk++) {
            int ke = kk * 16;
            uint32_t a0 = *(uint32_t*)&Ph[(rb + lr) * VSTR + ke + 2 * lc];
            uint32_t a1 = *(uint32_t*)&Ph[(rb + lr + 8) * VSTR + ke + 2 * lc];
            uint32_t a2 = *(uint32_t*)&Ph[(rb + lr) * VSTR + ke + 2 * lc + 8];
            uint32_t a3 = *(uint32_t*)&Ph[(rb + lr + 8) * VSTR + ke + 2 * lc + 8];
#pragma unroll
            for (int nt = 0; nt < 16; nt++) {
                int n = nt * 8 + lr;
                uint32_t bh0 = *(uint32_t*)&VTh[n * VSTR + ke + 2 * lc];
                uint32_t bh1 = *(uint32_t*)&VTh[n * VSTR + ke + 2 * lc + 8];
                uint32_t bl0 = *(uint32_t*)&VTl[n * VSTR + ke + 2 * lc];
                uint32_t bl1 = *(uint32_t*)&VTl[n * VSTR + ke + 2 * lc + 8];
                mmafp(O[nt], a0, a1, a2, a3, bh0, bh1);
                mmafp(O[nt], a0, a1, a2, a3, bl0, bl1);
            }
        }
    }

    // finalize: natural-order fp16 into g_at
    float inv0 = 1.f / l0r, inv1 = 1.f / l1r;
    __half* oa = g_at + (size_t)(b * T_ + q0) * DIM_ + h * HD_;
#pragma unroll
    for (int nt = 0; nt < 16; nt++) {
        int col = nt * 8 + 2 * lc;
        *(uint32_t*)&oa[(size_t)(rb + lr) * DIM_ + col]     = pack2h(O[nt][0] * inv0, O[nt][1] * inv0);
        *(uint32_t*)&oa[(size_t)(rb + lr + 8) * DIM_ + col] = pack2h(O[nt][2] * inv1, O[nt][3] * inv1);
    }
}

static const int FLASH_SMEM = (64 * KSTR + 2 * 128 * VSTR + 64 * VSTR) * 2;

// ---------------------------------------------------------------------------
extern "C" void kernel_launch(void* const* d_in, const int* in_sizes, int n_in,
                              void* d_out, int out_size)
{
    const float* x  = (const float*)d_in[0];
    const float* Wq = (const float*)d_in[1];
    const float* Wk = (const float*)d_in[2];
    const float* Wv = (const float*)d_in[3];
    const float* Wo = (const float*)d_in[4];

    float* out = (float*)d_out;                       // [B,T,DIM]
    float* pk  = out + (size_t)BT_ * DIM_;            // present_k [B,1,T,HD]
    float* pv  = pk + (size_t)BT_ * HD_;              // present_v [B,1,T,HD]

    cudaFuncSetAttribute(flash_mixed, cudaFuncAttributeMaxDynamicSharedMemorySize, FLASH_SMEM);
    cudaFuncSetAttribute(hgemm, cudaFuncAttributeMaxDynamicSharedMemorySize, GEMM_SMEM);

    // prep: fp16 conversions
    conv_act<<<(BT_ * DIM_ / 8) / 256, 256>>>(x);
    conv_w2<<<dim3(DIM_ / 32, DIM_ / 32, 2), dim3(32, 2)>>>(Wq, Wo, DIM_, 0, 3);
    conv_w2<<<dim3(HD_ / 32, DIM_ / 32, 2), dim3(32, 2)>>>(Wk, Wv, HD_, 1, 2);

    // fused Q/K/V projection: x tiles 0..15 = Q, 16 = K, 17 = V
    hgemm<<<dim3(18, BT_ / 128), 256, GEMM_SMEM>>>(0, pk, pv, nullptr);

    // RoPE + fp16 conversion (+ V transpose/split)
    rope_q_split<<<(BT_ * H_ * 64) / 256, 256>>>();
    rope_k_split<<<(BT_ * 64) / 256, 256>>>(pk);
    v_split_t<<<dim3(T_ / 32, HD_ / 32, B_), dim3(32, 8)>>>(pv);

    // Attention -> g_at (fp16, natural order; Wo A-operand)
    flash_mixed<<<dim3(T_ / FBQ, B_ * H_), 128, FLASH_SMEM>>>();

    // out = attn @ Wo
    hgemm<<<dim3(16, BT_ / 128), 256, GEMM_SMEM>>>(1, nullptr, nullptr, out);
}

// round 14
// speedup vs baseline: 1.0131x; 1.0131x over previous
#include <cuda_runtime.h>
#include <cuda_fp16.h>
#include <math.h>
#include <stdint.h>

#define B_ 2
#define T_ 2048
#define DIM_ 2048
#define H_ 16
#define HD_ 128
#define BT_ (B_ * T_)

// ---------------------------------------------------------------------------
// Scratch (alloc-free rules: __device__ globals)
// ---------------------------------------------------------------------------
static __device__ float g_q[(size_t)BT_ * DIM_];     // Q after GEMM (pre-RoPE)
static __device__ __half g_qh[(size_t)BT_ * DIM_];   // roped+scaled Q (fp16)
static __device__ __half g_kh[(size_t)BT_ * HD_];    // roped K (fp16) [B,T,HD]
static __device__ __half g_vth[(size_t)BT_ * HD_];   // V^T hi/lo fp16 [B,HD,T]
static __device__ __half g_vtl[(size_t)BT_ * HD_];
// fp16 natural-order operands for projection GEMMs
static __device__ __half g_xt[(size_t)BT_ * DIM_];
static __device__ __half g_at[(size_t)BT_ * DIM_];   // attn out (written by flash)
static __device__ __half g_wqt[(size_t)DIM_ * DIM_]; // W^T [N][K]
static __device__ __half g_wot[(size_t)DIM_ * DIM_];
static __device__ __half g_wkt[(size_t)HD_ * DIM_];
static __device__ __half g_wvt[(size_t)HD_ * DIM_];

// ---------------------------------------------------------------------------
// helpers
// ---------------------------------------------------------------------------
__device__ __forceinline__ uint32_t smem_u32(const void* p) {
    uint32_t a;
    asm("{ .reg .u64 t; cvta.to.shared.u64 t, %1; cvt.u32.u64 %0, t; }" : "=r"(a) : "l"(p));
    return a;
}
__device__ __forceinline__ void mmafp(float* c, uint32_t a0, uint32_t a1, uint32_t a2,
                                      uint32_t a3, uint32_t b0, uint32_t b1) {
    asm volatile(
        "mma.sync.aligned.m16n8k16.row.col.f32.f16.f16.f32 "
        "{%0,%1,%2,%3},{%4,%5,%6,%7},{%8,%9},{%0,%1,%2,%3};"
        : "+f"(c[0]), "+f"(c[1]), "+f"(c[2]), "+f"(c[3])
        : "r"(a0), "r"(a1), "r"(a2), "r"(a3), "r"(b0), "r"(b1));
}
__device__ __forceinline__ uint32_t pack2h(float a, float b) {
    __half2 p = __floats2half2_rn(a, b);
    return *(uint32_t*)&p;
}
#define LDSM4(r0, r1, r2, r3, a) \
    asm volatile("ldmatrix.sync.aligned.m8n8.x4.shared.b16 {%0,%1,%2,%3}, [%4];" \
                 : "=r"(r0), "=r"(r1), "=r"(r2), "=r"(r3) : "r"(a))
#define CPA16(d, s) asm volatile("cp.async.cg.shared.global [%0], [%1], 16;" :: "r"(d), "l"(s))
#define CPCOMMIT()  asm volatile("cp.async.commit_group;" ::: "memory")
#define CPWAIT1()   asm volatile("cp.async.wait_group 1;" ::: "memory")
#define CPWAIT0()   asm volatile("cp.async.wait_group 0;" ::: "memory")

// ---------------------------------------------------------------------------
// Prep: plain fp32 -> fp16
// ---------------------------------------------------------------------------
__global__ __launch_bounds__(256) void conv_act(const float* __restrict__ src)
{
    size_t i = (size_t)blockIdx.x * 256 + threadIdx.x;   // 8 floats per thread
    size_t base = i * 8;
    float4 v0 = *(const float4*)(src + base);
    float4 v1 = *(const float4*)(src + base + 4);
    uint4 o = make_uint4(pack2h(v0.x, v0.y), pack2h(v0.z, v0.w),
                         pack2h(v1.x, v1.y), pack2h(v1.z, v1.w));
    *(uint4*)(g_xt + base) = o;
}

// W [K=2048][N] -> Wt [N][K] fp16 (transpose); blockIdx.z picks (W0,W1)
__global__ void conv_w2(const float* __restrict__ W0, const float* __restrict__ W1,
                        int N, int wsel0, int wsel1)
{
    __shared__ float t[32][33];
    const float* W = blockIdx.z ? W1 : W0;
    int wsel = blockIdx.z ? wsel1 : wsel0;
    __half* dst = (wsel == 0) ? g_wqt : (wsel == 1) ? g_wkt : (wsel == 2) ? g_wvt : g_wot;
    int n0 = blockIdx.x * 32, k0 = blockIdx.y * 32;
    int tx = threadIdx.x, ty = threadIdx.y;          // (32, 2)
#pragma unroll
    for (int r = ty; r < 32; r += 2)
        t[r][tx] = W[(size_t)(k0 + r) * N + n0 + tx];
    __syncthreads();
    float f[16];
#pragma unroll
    for (int j = 0; j < 16; j++) f[j] = t[ty * 16 + j][tx];
    uint4 o0 = make_uint4(pack2h(f[0], f[1]), pack2h(f[2], f[3]),
                          pack2h(f[4], f[5]), pack2h(f[6], f[7]));
    uint4 o1 = make_uint4(pack2h(f[8], f[9]), pack2h(f[10], f[11]),
                          pack2h(f[12], f[13]), pack2h(f[14], f[15]));
    size_t o = (size_t)(n0 + tx) * DIM_ + k0 + ty * 16;
    *(uint4*)(dst + o)     = o0;
    *(uint4*)(dst + o + 8) = o1;
}

// ---------------------------------------------------------------------------
// FP16 GEMM: CTA tile 128x64, warp tile 32x32 (8 warps 4Mx2N), 3 CTAs/SM.
// ldmatrix + XOR-swizzled smem + 3-stage k64 cp.async pipeline.
// mode 0: fused QKV — grid.x 0..31 -> Q tile; 32,33 -> K; 34,35 -> V. A = g_xt.
// mode 1: Wo — A = g_at, C = out, grid.x 0..31.
// smem/stage: A 128x64 halfs 16KB + B 64x64 halfs 8KB; 3 stages = 72KB.
// ---------------------------------------------------------------------------
#define NSTG 3
#define STGA 16384
#define STGBB 8192
#define BOFF (NSTG * STGA)          // B region offset = 49152
static const int GEMM_SMEM = NSTG * (STGA + STGBB);   // 73728

__global__ __launch_bounds__(256, 3) void hgemm(
    int mode, float* __restrict__ pk, float* __restrict__ pv, float* __restrict__ outp)
{
    extern __shared__ __half smh[];
    const __half* Ag;
    const __half* Bg;
    float* C;
    int N, bn0;
    if (mode == 0) {
        Ag = g_xt;
        if (blockIdx.x < 32)      { Bg = g_wqt; C = g_q; N = DIM_; bn0 = blockIdx.x * 64; }
        else if (blockIdx.x < 34) { Bg = g_wkt; C = pk;  N = HD_;  bn0 = (blockIdx.x - 32) * 64; }
        else                      { Bg = g_wvt; C = pv;  N = HD_;  bn0 = (blockIdx.x - 34) * 64; }
    } else {
        Ag = g_at; Bg = g_wot; C = outp; N = DIM_; bn0 = blockIdx.x * 64;
    }

    const int K = DIM_;
    int tid = threadIdx.x;
    int bm0 = blockIdx.y * 128;
    int warp = tid >> 5, lane = tid & 31;
    int wm = (warp >> 1) * 32, wn = (warp & 1) * 32;
    int lr = lane >> 2, lc = lane & 3;
    uint32_t sbase = smem_u32(smh);

    float acc[2][4][4];
#pragma unroll
    for (int mt = 0; mt < 2; mt++)
#pragma unroll
        for (int nt = 0; nt < 4; nt++)
#pragma unroll
            for (int i = 0; i < 4; i++) acc[mt][nt][i] = 0.f;

    // ---- cp.async geometry ----
    // A: thread t -> row t>>1 (0..127), 4 chunks at units (t&1)*4 + 0..3
    // B: thread t -> row t>>2 (0..63),  2 chunks at units (t&3)*2 + 0..1
    int arow = tid >> 1, auh = (tid & 1) * 4;
    int brow = tid >> 2, buh = (tid & 3) * 2;
    uint32_t adst[4], bdst[2];
#pragma unroll
    for (int i = 0; i < 4; i++)
        adst[i] = (uint32_t)(arow * 128 + (((auh + i) ^ (arow & 7)) * 16));
#pragma unroll
    for (int i = 0; i < 2; i++)
        bdst[i] = (uint32_t)(brow * 128 + (((buh + i) ^ (brow & 7)) * 16));
    const __half* aS = Ag + (size_t)(bm0 + arow) * K + auh * 8;
    const __half* bS = Bg + (size_t)(bn0 + brow) * K + buh * 8;

#define ISSUE(st, k0) do { \
        uint32_t ab = sbase + (uint32_t)((st) * STGA); \
        uint32_t bb = sbase + (uint32_t)(BOFF + (st) * STGBB); \
        CPA16(ab + adst[0], aS + (k0));          CPA16(ab + adst[1], aS + (k0) + 8); \
        CPA16(ab + adst[2], aS + (k0) + 16);     CPA16(ab + adst[3], aS + (k0) + 24); \
        CPA16(bb + bdst[0], bS + (k0));          CPA16(bb + bdst[1], bS + (k0) + 8); \
        CPCOMMIT(); \
    } while (0)

    // ---- ldmatrix per-lane addressing (row pitch 128B, proven R11 mapping) ----
    int swz = lane & 7;
    int mhalf = (lane >> 3) & 1;
    int uhi = lane >> 4;
    uint32_t aroww = (uint32_t)((wm + mhalf * 8 + swz) * 128);
    uint32_t browb = (uint32_t)((wn + mhalf * 8 + swz) * 128);

    ISSUE(0, 0);
    ISSUE(1, 64);

    const int nT = K / 64;   // 32
    for (int t = 0; t < nT; t++) {
        if (t + 1 < nT) CPWAIT1(); else CPWAIT0();
        __syncthreads();
        if (t + 2 < nT) ISSUE((t + 2) % NSTG, (t + 2) * 64);

        int p = t % NSTG;
        uint32_t ab = sbase + (uint32_t)(p * STGA);
        uint32_t bb = sbase + (uint32_t)(BOFF + p * STGBB);
#pragma unroll
        for (int kb = 0; kb < 4; kb++) {
            uint32_t koff = (uint32_t)(((kb * 2 + uhi) ^ swz) * 16);
            uint32_t br0[4], br1[4];
            LDSM4(br0[0], br0[1], br0[2], br0[3], bb + browb + koff);
            LDSM4(br1[0], br1[1], br1[2], br1[3], bb + browb + 2048 + koff);
#pragma unroll
            for (int mt = 0; mt < 2; mt++) {
                uint32_t ar[4];
                LDSM4(ar[0], ar[1], ar[2], ar[3], ab + aroww + mt * 2048 + koff);
                mmafp(acc[mt][0], ar[0], ar[1], ar[2], ar[3], br0[0], br0[2]);
                mmafp(acc[mt][1], ar[0], ar[1], ar[2], ar[3], br0[1], br0[3]);
                mmafp(acc[mt][2], ar[0], ar[1], ar[2], ar[3], br1[0], br1[2]);
                mmafp(acc[mt][3], ar[0], ar[1], ar[2], ar[3], br1[1], br1[3]);
            }
        }
    }

#pragma unroll
    for (int mt = 0; mt < 2; mt++) {
        int row = bm0 + wm + mt * 16 + lr;
#pragma unroll
        for (int nt = 0; nt < 4; nt++) {
            int col = bn0 + wn + nt * 8 + lc * 2;
            *(float2*)&C[(size_t)row * N + col]       = make_float2(acc[mt][nt][0], acc[mt][nt][1]);
            *(float2*)&C[(size_t)(row + 8) * N + col] = make_float2(acc[mt][nt][2], acc[mt][nt][3]);
        }
    }
#undef ISSUE
}

// ---------------------------------------------------------------------------
// RoPE + conversion kernels
// ---------------------------------------------------------------------------
__global__ __launch_bounds__(256) void rope_q_split()
{
    int idx = blockIdx.x * 256 + threadIdx.x;
    int j = idx & 63;
    int h = (idx >> 6) & (H_ - 1);
    int t = (idx >> 10) & (T_ - 1);
    int b = idx >> 21;
    const float scale = 0.08838834764831845f;
    float inv = powf(10000.0f, -(float)j * (1.0f / 64.0f));
    float ang = (float)t * inv;
    float sv, cv;
    sincosf(ang, &sv, &cv);
    size_t base = (((size_t)b * T_ + t) * H_ + h) * (size_t)HD_;
    float x1 = g_q[base + j], x2 = g_q[base + j + 64];
    g_qh[base + j]      = __float2half((x1 * cv - x2 * sv) * scale);
    g_qh[base + j + 64] = __float2half((x2 * cv + x1 * sv) * scale);
}

__global__ __launch_bounds__(256) void rope_k_split(float* __restrict__ kb)
{
    int idx = blockIdx.x * 256 + threadIdx.x;
    int j = idx & 63;
    int t = (idx >> 6) & (T_ - 1);
    int b = idx >> 17;
    float inv = powf(10000.0f, -(float)j * (1.0f / 64.0f));
    float ang = (float)t * inv;
    float sv, cv;
    sincosf(ang, &sv, &cv);
    size_t base = ((size_t)b * T_ + t) * (size_t)HD_;
    float x1 = kb[base + j], x2 = kb[base + j + 64];
    float r1 = x1 * cv - x2 * sv;
    float r2 = x2 * cv + x1 * sv;
    kb[base + j] = r1;              // present_k output (fp32)
    kb[base + j + 64] = r2;
    g_kh[base + j]      = __float2half(r1);
    g_kh[base + j + 64] = __float2half(r2);
}

// V: [B,T,HD] fp32 -> [B,HD,T] fp16 hi/lo (transpose + split)
__global__ void v_split_t(const float* __restrict__ vb)
{
    __shared__ float tile[32][33];
    int t0 = blockIdx.x * 32, d0 = blockIdx.y * 32, b = blockIdx.z;
    int tx = threadIdx.x, ty = threadIdx.y;
#pragma unroll
    for (int r = ty; r < 32; r += 8)
        tile[r][tx] = vb[((size_t)b * T_ + t0 + r) * HD_ + d0 + tx];
    __syncthreads();
#pragma unroll
    for (int r = ty; r < 32; r += 8) {
        float v = tile[tx][r];
        __half hh = __float2half(v);
        size_t o = ((size_t)b * HD_ + d0 + r) * T_ + t0 + tx;
        g_vth[o] = hh;
        g_vtl[o] = __float2half(v - __half2float(hh));
    }
}

// ---------------------------------------------------------------------------
// Flash attention: S = fp16 x1, PV = fp16 x2 (V hi/lo). BQ=BKV=64, 128 thr.
// Output written as natural-order fp16 into g_at (Wo A-operand).
// ---------------------------------------------------------------------------
#define FBQ 64
#define FBKV 64
#define KSTR 136
#define VSTR 72

__global__ __launch_bounds__(128, 2) void flash_mixed()
{
    extern __shared__ __half smh2[];
    __half* Kh  = smh2;                     // [64][KSTR]
    __half* VTh = Kh + 64 * KSTR;           // [128][VSTR]
    __half* VTl = VTh + 128 * VSTR;
    __half* Ph  = VTl + 128 * VSTR;         // [64][VSTR]

    int tid = threadIdx.x;
    int w = tid >> 5, lane = tid & 31;
    int lr = lane >> 2, lc = lane & 3;
    int qb = blockIdx.x;
    int bh = (int)blockIdx.y;
    int b = bh >> 4, h = bh & 15;
    int q0 = qb * FBQ;
    int rb = w * 16;

    uint32_t qf[8][4];
    {
        const __half* qh = g_qh + (((size_t)b * T_ + q0) * H_ + h) * (size_t)HD_;
#pragma unroll
        for (int kk = 0; kk < 8; kk++) {
            int ke = kk * 16;
            qf[kk][0] = *(const uint32_t*)&qh[(size_t)(rb + lr) * DIM_ + ke + 2 * lc];
            qf[kk][1] = *(const uint32_t*)&qh[(size_t)(rb + lr + 8) * DIM_ + ke + 2 * lc];
            qf[kk][2] = *(const uint32_t*)&qh[(size_t)(rb + lr) * DIM_ + ke + 2 * lc + 8];
            qf[kk][3] = *(const uint32_t*)&qh[(size_t)(rb + lr + 8) * DIM_ + ke + 2 * lc + 8];
        }
    }

    float m0r = -1e30f, m1r = -1e30f, l0r = 0.f, l1r = 0.f;
    float O[16][4];
#pragma unroll
    for (int i = 0; i < 16; i++)
#pragma unroll
        for (int j = 0; j < 4; j++) O[i][j] = 0.f;

    const __half* kbh = g_kh + (size_t)b * T_ * HD_;
    const __half* vbh = g_vth + (size_t)b * HD_ * T_;
    const __half* vbl = g_vtl + (size_t)b * HD_ * T_;

    for (int kt = 0; kt <= qb; kt++) {
        int k0 = kt * FBKV;
        __syncthreads();

#pragma unroll
        for (int it = 0; it < 8; it++) {
            int i = tid + it * 128;
            int r = i >> 4, c = (i & 15) * 8;
            *(uint4*)&Kh[r * KSTR + c] = *(const uint4*)&kbh[(size_t)(k0 + r) * HD_ + c];
        }
#pragma unroll
        for (int it = 0; it < 8; it++) {
            int i = tid + it * 128;
            int r = i >> 3, c = (i & 7) * 8;
            size_t ga = (size_t)r * T_ + k0 + c;
            *(uint4*)&VTh[r * VSTR + c] = *(const uint4*)&vbh[ga];
            *(uint4*)&VTl[r * VSTR + c] = *(const uint4*)&vbl[ga];
        }
        __syncthreads();

        float sacc[8][4];
#pragma unroll
        for (int nt = 0; nt < 8; nt++)
#pragma unroll
            for (int j = 0; j < 4; j++) sacc[nt][j] = 0.f;

#pragma unroll
        for (int kk = 0; kk < 8; kk++) {
            int ke = kk * 16;
#pragma unroll
            for (int nt = 0; nt < 8; nt++) {
                int n = nt * 8 + lr;
                uint32_t b0 = *(uint32_t*)&Kh[n * KSTR + ke + 2 * lc];
                uint32_t b1 = *(uint32_t*)&Kh[n * KSTR + ke + 2 * lc + 8];
                mmafp(sacc[nt], qf[kk][0], qf[kk][1], qf[kk][2], qf[kk][3], b0, b1);
            }
        }

        if (kt == qb) {
            int r0g = rb + lr, r1g = r0g + 8;
#pragma unroll
            for (int nt = 0; nt < 8; nt++) {
                int cg = nt * 8 + 2 * lc;
                if (cg > r0g)     sacc[nt][0] = -1e30f;
                if (cg + 1 > r0g) sacc[nt][1] = -1e30f;
                if (cg > r1g)     sacc[nt][2] = -1e30f;
                if (cg + 1 > r1g) sacc[nt][3] = -1e30f;
            }
        }

        float mt0 = -1e30f, mt1 = -1e30f;
#pragma unroll
        for (int nt = 0; nt < 8; nt++) {
            mt0 = fmaxf(mt0, fmaxf(sacc[nt][0], sacc[nt][1]));
            mt1 = fmaxf(mt1, fmaxf(sacc[nt][2], sacc[nt][3]));
        }
        mt0 = fmaxf(mt0, __shfl_xor_sync(0xffffffff, mt0, 1));
        mt0 = fmaxf(mt0, __shfl_xor_sync(0xffffffff, mt0, 2));
        mt1 = fmaxf(mt1, __shfl_xor_sync(0xffffffff, mt1, 1));
        mt1 = fmaxf(mt1, __shfl_xor_sync(0xffffffff, mt1, 2));

        float mn0 = fmaxf(m0r, mt0), mn1 = fmaxf(m1r, mt1);
        float al0f = __expf(m0r - mn0), al1f = __expf(m1r - mn1);
        m0r = mn0; m1r = mn1;

        float rs0 = 0.f, rs1 = 0.f;
#pragma unroll
        for (int nt = 0; nt < 8; nt++) {
            float p0 = __expf(sacc[nt][0] - mn0);
            float p1 = __expf(sacc[nt][1] - mn0);
            float p2 = __expf(sacc[nt][2] - mn1);
            float p3 = __expf(sacc[nt][3] - mn1);
            rs0 += p0 + p1; rs1 += p2 + p3;
            *(uint32_t*)&Ph[(rb + lr) * VSTR + nt * 8 + 2 * lc]     = pack2h(p0, p1);
            *(uint32_t*)&Ph[(rb + lr + 8) * VSTR + nt * 8 + 2 * lc] = pack2h(p2, p3);
        }
        rs0 += __shfl_xor_sync(0xffffffff, rs0, 1);
        rs0 += __shfl_xor_sync(0xffffffff, rs0, 2);
        rs1 += __shfl_xor_sync(0xffffffff, rs1, 1);
        rs1 += __shfl_xor_sync(0xffffffff, rs1, 2);
        l0r = l0r * al0f + rs0;
        l1r = l1r * al1f + rs1;

#pragma unroll
        for (int nt = 0; nt < 16; nt++) {
            O[nt][0] *= al0f; O[nt][1] *= al0f;
            O[nt][2] *= al1f; O[nt][3] *= al1f;
        }
        __syncwarp();

#pragma unroll
        for (int kk = 0; kk < 4; kk++) {
            int ke = kk * 16;
            uint32_t a0 = *(uint32_t*)&Ph[(rb + lr) * VSTR + ke + 2 * lc];
            uint32_t a1 = *(uint32_t*)&Ph[(rb + lr + 8) * VSTR + ke + 2 * lc];
            uint32_t a2 = *(uint32_t*)&Ph[(rb + lr) * VSTR + ke + 2 * lc + 8];
            uint32_t a3 = *(uint32_t*)&Ph[(rb + lr + 8) * VSTR + ke + 2 * lc + 8];
#pragma unroll
            for (int nt = 0; nt < 16; nt++) {
                int n = nt * 8 + lr;
                uint32_t bh0 = *(uint32_t*)&VTh[n * VSTR + ke + 2 * lc];
                uint32_t bh1 = *(uint32_t*)&VTh[n * VSTR + ke + 2 * lc + 8];
                uint32_t bl0 = *(uint32_t*)&VTl[n * VSTR + ke + 2 * lc];
                uint32_t bl1 = *(uint32_t*)&VTl[n * VSTR + ke + 2 * lc + 8];
                mmafp(O[nt], a0, a1, a2, a3, bh0, bh1);
                mmafp(O[nt], a0, a1, a2, a3, bl0, bl1);
            }
        }
    }

    float inv0 = 1.f / l0r, inv1 = 1.f / l1r;
    __half* oa = g_at + (size_t)(b * T_ + q0) * DIM_ + h * HD_;
#pragma unroll
    for (int nt = 0; nt < 16; nt++) {
        int col = nt * 8 + 2 * lc;
        *(uint32_t*)&oa[(size_t)(rb + lr) * DIM_ + col]     = pack2h(O[nt][0] * inv0, O[nt][1] * inv0);
        *(uint32_t*)&oa[(size_t)(rb + lr + 8) * DIM_ + col] = pack2h(O[nt][2] * inv1, O[nt][3] * inv1);
    }
}

static const int FLASH_SMEM = (64 * KSTR + 2 * 128 * VSTR + 64 * VSTR) * 2;

// ---------------------------------------------------------------------------
extern "C" void kernel_launch(void* const* d_in, const int* in_sizes, int n_in,
                              void* d_out, int out_size)
{
    const float* x  = (const float*)d_in[0];
    const float* Wq = (const float*)d_in[1];
    const float* Wk = (const float*)d_in[2];
    const float* Wv = (const float*)d_in[3];
    const float* Wo = (const float*)d_in[4];

    float* out = (float*)d_out;                       // [B,T,DIM]
    float* pk  = out + (size_t)BT_ * DIM_;            // present_k [B,1,T,HD]
    float* pv  = pk + (size_t)BT_ * HD_;              // present_v [B,1,T,HD]

    cudaFuncSetAttribute(flash_mixed, cudaFuncAttributeMaxDynamicSharedMemorySize, FLASH_SMEM);
    cudaFuncSetAttribute(hgemm, cudaFuncAttributeMaxDynamicSharedMemorySize, GEMM_SMEM);

    // prep: fp16 conversions
    conv_act<<<(BT_ * DIM_ / 8) / 256, 256>>>(x);
    conv_w2<<<dim3(DIM_ / 32, DIM_ / 32, 2), dim3(32, 2)>>>(Wq, Wo, DIM_, 0, 3);
    conv_w2<<<dim3(HD_ / 32, DIM_ / 32, 2), dim3(32, 2)>>>(Wk, Wv, HD_, 1, 2);

    // fused Q/K/V projection: x tiles 0..31 = Q, 32,33 = K, 34,35 = V
    hgemm<<<dim3(36, BT_ / 128), 256, GEMM_SMEM>>>(0, pk, pv, nullptr);

    // RoPE + fp16 conversion (+ V transpose/split)
    rope_q_split<<<(BT_ * H_ * 64) / 256, 256>>>();
    rope_k_split<<<(BT_ * 64) / 256, 256>>>(pk);
    v_split_t<<<dim3(T_ / 32, HD_ / 32, B_), dim3(32, 8)>>>(pv);

    // Attention -> g_at (fp16, natural order; Wo A-operand)
    flash_mixed<<<dim3(T_ / FBQ, B_ * H_), 128, FLASH_SMEM>>>();

    // out = attn @ Wo
    hgemm<<<dim3(32, BT_ / 128), 256, GEMM_SMEM>>>(1, nullptr, nullptr, out);
}

// round 16
// speedup vs baseline: 1.0805x; 1.0665x over previous
#include <cuda_runtime.h>
#include <cuda_fp16.h>
#include <math.h>
#include <stdint.h>

#define B_ 2
#define T_ 2048
#define DIM_ 2048
#define H_ 16
#define HD_ 128
#define BT_ (B_ * T_)

// ---------------------------------------------------------------------------
// Scratch (alloc-free rules: __device__ globals)
// ---------------------------------------------------------------------------
static __device__ float g_q[(size_t)BT_ * DIM_];     // Q after GEMM (pre-RoPE)
static __device__ __half g_qh[(size_t)BT_ * DIM_];   // roped+scaled Q (fp16)
static __device__ __half g_kh[(size_t)BT_ * HD_];    // roped K (fp16) [B,T,HD]
static __device__ __half g_vth[(size_t)BT_ * HD_];   // V^T fp16 [B,HD,T]
// fp16 k-pair-permuted operands for projection GEMMs (uint32 = 2 halfs)
static __device__ uint32_t g_xt[(size_t)BT_ * DIM_ / 2];
static __device__ uint32_t g_at[(size_t)BT_ * DIM_ / 2];    // attn out (written by flash)
static __device__ uint32_t g_wqt[(size_t)DIM_ * DIM_ / 2];  // W^T [N][K]
static __device__ uint32_t g_wot[(size_t)DIM_ * DIM_ / 2];
static __device__ uint32_t g_wkt[(size_t)HD_ * DIM_ / 2];
static __device__ uint32_t g_wvt[(size_t)HD_ * DIM_ / 2];

// ---------------------------------------------------------------------------
// helpers
// ---------------------------------------------------------------------------
__device__ __forceinline__ uint32_t smem_u32(const void* p) {
    uint32_t a;
    asm("{ .reg .u64 t; cvta.to.shared.u64 t, %1; cvt.u32.u64 %0, t; }" : "=r"(a) : "l"(p));
    return a;
}
__device__ __forceinline__ void mmafp(float* c, uint32_t a0, uint32_t a1, uint32_t a2,
                                      uint32_t a3, uint32_t b0, uint32_t b1) {
    asm volatile(
        "mma.sync.aligned.m16n8k16.row.col.f32.f16.f16.f32 "
        "{%0,%1,%2,%3},{%4,%5,%6,%7},{%8,%9},{%0,%1,%2,%3};"
        : "+f"(c[0]), "+f"(c[1]), "+f"(c[2]), "+f"(c[3])
        : "r"(a0), "r"(a1), "r"(a2), "r"(a3), "r"(b0), "r"(b1));
}
__device__ __forceinline__ uint32_t pack2h(float a, float b) {
    __half2 p = __floats2half2_rn(a, b);
    return *(uint32_t*)&p;
}
#define CPA16(d, s) asm volatile("cp.async.cg.shared.global [%0], [%1], 16;" :: "r"(d), "l"(s))
#define CPCOMMIT()  asm volatile("cp.async.commit_group;" ::: "memory")
#define CPWAIT2()   asm volatile("cp.async.wait_group 2;" ::: "memory")

// ---------------------------------------------------------------------------
// Prep: fp32 -> fp16, k-pair permutation within 16-blocks:
// word w: w=2g -> halfs (k=2g,2g+1); w=2g+1 -> (2g+8,2g+9)
// ---------------------------------------------------------------------------
__global__ __launch_bounds__(256) void conv_act(const float* __restrict__ src)
{
    size_t i = (size_t)blockIdx.x * 256 + threadIdx.x;   // one 16-float block
    size_t base = i * 16;
    float f[16];
#pragma unroll
    for (int j = 0; j < 16; j += 4) *(float4*)(f + j) = *(const float4*)(src + base + j);
    uint32_t w[8];
#pragma unroll
    for (int g = 0; g < 4; g++) {
        w[2 * g]     = pack2h(f[2 * g], f[2 * g + 1]);
        w[2 * g + 1] = pack2h(f[2 * g + 8], f[2 * g + 9]);
    }
    *(uint4*)(g_xt + i * 8)     = make_uint4(w[0], w[1], w[2], w[3]);
    *(uint4*)(g_xt + i * 8 + 4) = make_uint4(w[4], w[5], w[6], w[7]);
}

// W [K=2048][N] -> Wt [N][K] fp16, k-pair-permuted; blockIdx.z picks (W0,W1)
__global__ void conv_w2(const float* __restrict__ W0, const float* __restrict__ W1,
                        int N, int wsel0, int wsel1)
{
    __shared__ float t[32][33];
    const float* W = blockIdx.z ? W1 : W0;
    int wsel = blockIdx.z ? wsel1 : wsel0;
    uint32_t* dst = (wsel == 0) ? g_wqt : (wsel == 1) ? g_wkt : (wsel == 2) ? g_wvt : g_wot;
    int n0 = blockIdx.x * 32, k0 = blockIdx.y * 32;
    int tx = threadIdx.x, ty = threadIdx.y;          // (32, 2)
#pragma unroll
    for (int r = ty; r < 32; r += 2)
        t[r][tx] = W[(size_t)(k0 + r) * N + n0 + tx];
    __syncthreads();
    float f[16];
#pragma unroll
    for (int j = 0; j < 16; j++) f[j] = t[ty * 16 + j][tx];
    uint32_t w[8];
#pragma unroll
    for (int g = 0; g < 4; g++) {
        w[2 * g]     = pack2h(f[2 * g], f[2 * g + 1]);
        w[2 * g + 1] = pack2h(f[2 * g + 8], f[2 * g + 9]);
    }
    size_t o = (size_t)(n0 + tx) * (DIM_ / 2) + (size_t)(k0 + ty * 16) / 2;
    *(uint4*)(dst + o)     = make_uint4(w[0], w[1], w[2], w[3]);
    *(uint4*)(dst + o + 4) = make_uint4(w[4], w[5], w[6], w[7]);
}

// ---------------------------------------------------------------------------
// FP16 GEMM, 4-stage cp.async pipeline (R10 best-measured config).
// mode 0: fused QKV — grid.x 0..15 -> Q tile; 16 -> K; 17 -> V.  A = g_xt.
// mode 1: Wo — A = g_at, C = out.
// 128x128 tile, stage = k32, 256 thr (8 warps 2x4, warp 64x32).
// ---------------------------------------------------------------------------
__global__ __launch_bounds__(256, 2) void hgemm(
    int mode, float* __restrict__ pk, float* __restrict__ pv, float* __restrict__ outp)
{
    extern __shared__ uint32_t sm4[];
    const uint32_t* Ag;
    const uint32_t* Bg;
    float* C;
    int N, bn0;
    if (mode == 0) {
        Ag = g_xt;
        if (blockIdx.x < 16)      { Bg = g_wqt; C = g_q; N = DIM_; bn0 = blockIdx.x * 128; }
        else if (blockIdx.x == 16){ Bg = g_wkt; C = pk;  N = HD_;  bn0 = 0; }
        else                      { Bg = g_wvt; C = pv;  N = HD_;  bn0 = 0; }
    } else {
        Ag = g_at; Bg = g_wot; C = outp; N = DIM_; bn0 = blockIdx.x * 128;
    }

    const int KW = DIM_ / 2;   // uint32 words per row
    int tid = threadIdx.x;
    int bm0 = blockIdx.y * 128;
    int warp = tid >> 5, lane = tid & 31;
    int wm = (warp & 1) * 64, wn = (warp >> 1) * 32;
    int lr = lane >> 2, lc = lane & 3;
    uint32_t sbase = smem_u32(sm4);

    float acc[4][4][4];
#pragma unroll
    for (int mt = 0; mt < 4; mt++)
#pragma unroll
        for (int nt = 0; nt < 4; nt++)
#pragma unroll
            for (int i = 0; i < 4; i++) acc[mt][nt][i] = 0.f;

    int c0row = tid >> 2, c0part = tid & 3;
    int c1row = c0row + 64;
    uint32_t d0 = (uint32_t)((((c0part >> 1) * 1024) + c0row * 8 + (c0part & 1) * 4) * 4);
    uint32_t d1 = (uint32_t)((((c0part >> 1) * 1024) + c1row * 8 + (c0part & 1) * 4) * 4);
    int koff = (c0part >> 1) * 8 + (c0part & 1) * 4;
    const uint32_t* a0p = Ag + (size_t)(bm0 + c0row) * KW + koff;
    const uint32_t* a1p = Ag + (size_t)(bm0 + c1row) * KW + koff;
    const uint32_t* b0p = Bg + (size_t)(bn0 + c0row) * KW + koff;
    const uint32_t* b1p = Bg + (size_t)(bn0 + c1row) * KW + koff;

#define ISSUE(st, k0) do { \
        uint32_t sb = sbase + (uint32_t)((st) * 8192); \
        CPA16(sb + d0, a0p + (k0)); \
        CPA16(sb + d1, a1p + (k0)); \
        CPA16(sb + 32768 + d0, b0p + (k0)); \
        CPA16(sb + 32768 + d1, b1p + (k0)); \
        CPCOMMIT(); \
    } while (0)

    ISSUE(0, 0);
    ISSUE(1, 16);
    ISSUE(2, 32);

    const int nk = 64;   // k32 per iter
    for (int t = 0; t < nk; t++) {
        int p = t & 3;
        CPWAIT2();
        __syncthreads();
        if (t + 3 < nk) { ISSUE((t + 3) & 3, (t + 3) * 16); }
        else CPCOMMIT();

#pragma unroll
        for (int kb = 0; kb < 2; kb++) {
            int ab = p * 2048 + kb * 1024;
            int bb = 8192 + p * 2048 + kb * 1024;
            uint2 bfr[4];
#pragma unroll
            for (int nt = 0; nt < 4; nt++)
                bfr[nt] = *(uint2*)&sm4[bb + (wn + nt * 8 + lr) * 8 + lc * 2];
#pragma unroll
            for (int mt = 0; mt < 4; mt++) {
                uint2 alo = *(uint2*)&sm4[ab + (wm + mt * 16 + lr) * 8 + lc * 2];
                uint2 ahi = *(uint2*)&sm4[ab + (wm + mt * 16 + lr + 8) * 8 + lc * 2];
#pragma unroll
                for (int nt = 0; nt < 4; nt++)
                    mmafp(acc[mt][nt], alo.x, ahi.x, alo.y, ahi.y, bfr[nt].x, bfr[nt].y);
            }
        }
    }

#pragma unroll
    for (int mt = 0; mt < 4; mt++) {
        int row = bm0 + wm + mt * 16 + lr;
#pragma unroll
        for (int nt = 0; nt < 4; nt++) {
            int col = bn0 + wn + nt * 8 + lc * 2;
            *(float2*)&C[(size_t)row * N + col]       = make_float2(acc[mt][nt][0], acc[mt][nt][1]);
            *(float2*)&C[(size_t)(row + 8) * N + col] = make_float2(acc[mt][nt][2], acc[mt][nt][3]);
        }
    }
#undef ISSUE
}

// ---------------------------------------------------------------------------
// RoPE + conversion kernels
// ---------------------------------------------------------------------------
__global__ __launch_bounds__(256) void rope_q_split()
{
    int idx = blockIdx.x * 256 + threadIdx.x;
    int j = idx & 63;
    int h = (idx >> 6) & (H_ - 1);
    int t = (idx >> 10) & (T_ - 1);
    int b = idx >> 21;
    const float scale = 0.08838834764831845f;
    float inv = powf(10000.0f, -(float)j * (1.0f / 64.0f));
    float ang = (float)t * inv;
    float sv, cv;
    sincosf(ang, &sv, &cv);
    size_t base = (((size_t)b * T_ + t) * H_ + h) * (size_t)HD_;
    float x1 = g_q[base + j], x2 = g_q[base + j + 64];
    g_qh[base + j]      = __float2half((x1 * cv - x2 * sv) * scale);
    g_qh[base + j + 64] = __float2half((x2 * cv + x1 * sv) * scale);
}

__global__ __launch_bounds__(256) void rope_k_split(float* __restrict__ kb)
{
    int idx = blockIdx.x * 256 + threadIdx.x;
    int j = idx & 63;
    int t = (idx >> 6) & (T_ - 1);
    int b = idx >> 17;
    float inv = powf(10000.0f, -(float)j * (1.0f / 64.0f));
    float ang = (float)t * inv;
    float sv, cv;
    sincosf(ang, &sv, &cv);
    size_t base = ((size_t)b * T_ + t) * (size_t)HD_;
    float x1 = kb[base + j], x2 = kb[base + j + 64];
    float r1 = x1 * cv - x2 * sv;
    float r2 = x2 * cv + x1 * sv;
    kb[base + j] = r1;              // present_k output (fp32)
    kb[base + j + 64] = r2;
    g_kh[base + j]      = __float2half(r1);
    g_kh[base + j + 64] = __float2half(r2);
}

// V: [B,T,HD] fp32 -> [B,HD,T] fp16 (transpose)
__global__ void v_split_t(const float* __restrict__ vb)
{
    __shared__ float tile[32][33];
    int t0 = blockIdx.x * 32, d0 = blockIdx.y * 32, b = blockIdx.z;
    int tx = threadIdx.x, ty = threadIdx.y;
#pragma unroll
    for (int r = ty; r < 32; r += 8)
        tile[r][tx] = vb[((size_t)b * T_ + t0 + r) * HD_ + d0 + tx];
    __syncthreads();
#pragma unroll
    for (int r = ty; r < 32; r += 8) {
        size_t o = ((size_t)b * HD_ + d0 + r) * T_ + t0 + tx;
        g_vth[o] = __float2half(tile[tx][r]);
    }
}

// ---------------------------------------------------------------------------
// Flash attention: S = fp16 x1, PV = fp16 x1. BQ=BKV=64, 128 thr, 3 CTAs/SM.
// Output written directly as k-pair-permuted fp16 into g_at (Wo A-operand).
// ---------------------------------------------------------------------------
#define FBQ 64
#define FBKV 64
#define KSTR 136
#define VSTR 72

__global__ __launch_bounds__(128, 3) void flash_mixed()
{
    extern __shared__ __half smh[];
    __half* Kh  = smh;                      // [64][KSTR]
    __half* VTh = Kh + 64 * KSTR;           // [128][VSTR]
    __half* Ph  = VTh + 128 * VSTR;         // [64][VSTR]

    int tid = threadIdx.x;
    int w = tid >> 5, lane = tid & 31;
    int lr = lane >> 2, lc = lane & 3;
    int qb = blockIdx.x;
    int bh = (int)blockIdx.y;
    int b = bh >> 4, h = bh & 15;
    int q0 = qb * FBQ;
    int rb = w * 16;

    // Q fragments (fp16) in registers
    uint32_t qf[8][4];
    {
        const __half* qh = g_qh + (((size_t)b * T_ + q0) * H_ + h) * (size_t)HD_;
#pragma unroll
        for (int kk = 0; kk < 8; kk++) {
            int ke = kk * 16;
            qf[kk][0] = *(const uint32_t*)&qh[(size_t)(rb + lr) * DIM_ + ke + 2 * lc];
            qf[kk][1] = *(const uint32_t*)&qh[(size_t)(rb + lr + 8) * DIM_ + ke + 2 * lc];
            qf[kk][2] = *(const uint32_t*)&qh[(size_t)(rb + lr) * DIM_ + ke + 2 * lc + 8];
            qf[kk][3] = *(const uint32_t*)&qh[(size_t)(rb + lr + 8) * DIM_ + ke + 2 * lc + 8];
        }
    }

    float m0r = -1e30f, m1r = -1e30f, l0r = 0.f, l1r = 0.f;
    float O[16][4];
#pragma unroll
    for (int i = 0; i < 16; i++)
#pragma unroll
        for (int j = 0; j < 4; j++) O[i][j] = 0.f;

    const __half* kbh = g_kh + (size_t)b * T_ * HD_;
    const __half* vbh = g_vth + (size_t)b * HD_ * T_;

    for (int kt = 0; kt <= qb; kt++) {
        int k0 = kt * FBKV;
        __syncthreads();

        // K tile: 64 x 128 fp16
#pragma unroll
        for (int it = 0; it < 8; it++) {
            int i = tid + it * 128;
            int r = i >> 4, c = (i & 15) * 8;
            *(uint4*)&Kh[r * KSTR + c] = *(const uint4*)&kbh[(size_t)(k0 + r) * HD_ + c];
        }
        // V^T tile: 128 x 64 fp16
#pragma unroll
        for (int it = 0; it < 8; it++) {
            int i = tid + it * 128;
            int r = i >> 3, c = (i & 7) * 8;
            *(uint4*)&VTh[r * VSTR + c] = *(const uint4*)&vbh[(size_t)r * T_ + k0 + c];
        }
        __syncthreads();

        // S = Q @ K^T (fp16 x1)
        float sacc[8][4];
#pragma unroll
        for (int nt = 0; nt < 8; nt++)
#pragma unroll
            for (int j = 0; j < 4; j++) sacc[nt][j] = 0.f;

#pragma unroll
        for (int kk = 0; kk < 8; kk++) {
            int ke = kk * 16;
#pragma unroll
            for (int nt = 0; nt < 8; nt++) {
                int n = nt * 8 + lr;
                uint32_t b0 = *(uint32_t*)&Kh[n * KSTR + ke + 2 * lc];
                uint32_t b1 = *(uint32_t*)&Kh[n * KSTR + ke + 2 * lc + 8];
                mmafp(sacc[nt], qf[kk][0], qf[kk][1], qf[kk][2], qf[kk][3], b0, b1);
            }
        }

        if (kt == qb) {
            int r0g = rb + lr, r1g = r0g + 8;
#pragma unroll
            for (int nt = 0; nt < 8; nt++) {
                int cg = nt * 8 + 2 * lc;
                if (cg > r0g)     sacc[nt][0] = -1e30f;
                if (cg + 1 > r0g) sacc[nt][1] = -1e30f;
                if (cg > r1g)     sacc[nt][2] = -1e30f;
                if (cg + 1 > r1g) sacc[nt][3] = -1e30f;
            }
        }

        float mt0 = -1e30f, mt1 = -1e30f;
#pragma unroll
        for (int nt = 0; nt < 8; nt++) {
            mt0 = fmaxf(mt0, fmaxf(sacc[nt][0], sacc[nt][1]));
            mt1 = fmaxf(mt1, fmaxf(sacc[nt][2], sacc[nt][3]));
        }
        mt0 = fmaxf(mt0, __shfl_xor_sync(0xffffffff, mt0, 1));
        mt0 = fmaxf(mt0, __shfl_xor_sync(0xffffffff, mt0, 2));
        mt1 = fmaxf(mt1, __shfl_xor_sync(0xffffffff, mt1, 1));
        mt1 = fmaxf(mt1, __shfl_xor_sync(0xffffffff, mt1, 2));

        float mn0 = fmaxf(m0r, mt0), mn1 = fmaxf(m1r, mt1);
        float al0f = __expf(m0r - mn0), al1f = __expf(m1r - mn1);
        m0r = mn0; m1r = mn1;

        float rs0 = 0.f, rs1 = 0.f;
#pragma unroll
        for (int nt = 0; nt < 8; nt++) {
            float p0 = __expf(sacc[nt][0] - mn0);
            float p1 = __expf(sacc[nt][1] - mn0);
            float p2 = __expf(sacc[nt][2] - mn1);
            float p3 = __expf(sacc[nt][3] - mn1);
            rs0 += p0 + p1; rs1 += p2 + p3;
            *(uint32_t*)&Ph[(rb + lr) * VSTR + nt * 8 + 2 * lc]     = pack2h(p0, p1);
            *(uint32_t*)&Ph[(rb + lr + 8) * VSTR + nt * 8 + 2 * lc] = pack2h(p2, p3);
        }
        rs0 += __shfl_xor_sync(0xffffffff, rs0, 1);
        rs0 += __shfl_xor_sync(0xffffffff, rs0, 2);
        rs1 += __shfl_xor_sync(0xffffffff, rs1, 1);
        rs1 += __shfl_xor_sync(0xffffffff, rs1, 2);
        l0r = l0r * al0f + rs0;
        l1r = l1r * al1f + rs1;

#pragma unroll
        for (int nt = 0; nt < 16; nt++) {
            O[nt][0] *= al0f; O[nt][1] *= al0f;
            O[nt][2] *= al1f; O[nt][3] *= al1f;
        }
        __syncwarp();

        // O += P @ V (fp16 x1)
#pragma unroll
        for (int kk = 0; kk < 4; kk++) {
            int ke = kk * 16;
            uint32_t a0 = *(uint32_t*)&Ph[(rb + lr) * VSTR + ke + 2 * lc];
            uint32_t a1 = *(uint32_t*)&Ph[(rb + lr + 8) * VSTR + ke + 2 * lc];
            uint32_t a2 = *(uint32_t*)&Ph[(rb + lr) * VSTR + ke + 2 * lc + 8];
            uint32_t a3 = *(uint32_t*)&Ph[(rb + lr + 8) * VSTR + ke + 2 * lc + 8];
#pragma unroll
            for (int nt = 0; nt < 16; nt++) {
                int n = nt * 8 + lr;
                uint32_t bh0 = *(uint32_t*)&VTh[n * VSTR + ke + 2 * lc];
                uint32_t bh1 = *(uint32_t*)&VTh[n * VSTR + ke + 2 * lc + 8];
                mmafp(O[nt], a0, a1, a2, a3, bh0, bh1);
            }
        }
    }

    // finalize: k-pair-permuted fp16 directly into g_at [row][word]
    // col = h*128 + nt*8 + 2*lc ; word = (h*8 + nt/2)*8 + 2*lc + (nt&1)
    float inv0 = 1.f / l0r, inv1 = 1.f / l1r;
    uint32_t* oa = g_at + (size_t)(b * T_ + q0) * (DIM_ / 2);
#pragma unroll
    for (int nt = 0; nt < 16; nt++) {
        int word = (h * 8 + (nt >> 1)) * 8 + 2 * lc + (nt & 1);
        oa[(size_t)(rb + lr) * (DIM_ / 2) + word]     = pack2h(O[nt][0] * inv0, O[nt][1] * inv0);
        oa[(size_t)(rb + lr + 8) * (DIM_ / 2) + word] = pack2h(O[nt][2] * inv1, O[nt][3] * inv1);
    }
}

static const int FLASH_SMEM = (64 * KSTR + 128 * VSTR + 64 * VSTR) * 2;
static const int GEMM_SMEM = 65536;

// ---------------------------------------------------------------------------
extern "C" void kernel_launch(void* const* d_in, const int* in_sizes, int n_in,
                              void* d_out, int out_size)
{
    const float* x  = (const float*)d_in[0];
    const float* Wq = (const float*)d_in[1];
    const float* Wk = (const float*)d_in[2];
    const float* Wv = (const float*)d_in[3];
    const float* Wo = (const float*)d_in[4];

    float* out = (float*)d_out;                       // [B,T,DIM]
    float* pk  = out + (size_t)BT_ * DIM_;            // present_k [B,1,T,HD]
    float* pv  = pk + (size_t)BT_ * HD_;              // present_v [B,1,T,HD]

    cudaFuncSetAttribute(flash_mixed, cudaFuncAttributeMaxDynamicSharedMemorySize, FLASH_SMEM);
    cudaFuncSetAttribute(hgemm, cudaFuncAttributeMaxDynamicSharedMemorySize, GEMM_SMEM);

    // prep: fp16 conversions (3 launches)
    conv_act<<<(BT_ * DIM_ / 16) / 256, 256>>>(x);
    conv_w2<<<dim3(DIM_ / 32, DIM_ / 32, 2), dim3(32, 2)>>>(Wq, Wo, DIM_, 0, 3);
    conv_w2<<<dim3(HD_ / 32, DIM_ / 32, 2), dim3(32, 2)>>>(Wk, Wv, HD_, 1, 2);

    // fused Q/K/V projection: x tiles 0..15 = Q, 16 = K, 17 = V
    hgemm<<<dim3(18, BT_ / 128), 256, GEMM_SMEM>>>(0, pk, pv, nullptr);

    // RoPE + fp16 conversion (+ V transpose)
    rope_q_split<<<(BT_ * H_ * 64) / 256, 256>>>();
    rope_k_split<<<(BT_ * 64) / 256, 256>>>(pk);
    v_split_t<<<dim3(T_ / 32, HD_ / 32, B_), dim3(32, 8)>>>(pv);

    // Attention -> g_at (fp16, permuted; Wo A-operand)
    flash_mixed<<<dim3(T_ / FBQ, B_ * H_), 128, FLASH_SMEM>>>();

    // out = attn @ Wo
    hgemm<<<dim3(16, BT_ / 128), 256, GEMM_SMEM>>>(1, nullptr, nullptr, out);
}